// round 3
// baseline (speedup 1.0000x reference)
#include <cuda_runtime.h>
#include <cstdint>

// Problem dims
#define G1 512
#define E_EDGES 16384
#define S1 8192
#define S2 8192
#define BATCH 256
#define PAD 20            // floats per staged x row (16 data + 4 pad; 16B-aligned, odd in 16B units)

typedef unsigned long long ull;

// -------- device scratch (no allocations allowed) --------
__device__ int g_offsets[G1 + 1];
__device__ int g_edge_list[E_EDGES];   // packed: (t1 << 16) | e

// -------- fused precompute: histogram + scan + scatter, one CTA --------
__global__ __launch_bounds__(512) void bucket_kernel(const int* __restrict__ ei) {
    __shared__ int cnt[G1];
    __shared__ int scn[G1];
    __shared__ int cur[G1];
    const int t = threadIdx.x;
    cnt[t] = 0;
    __syncthreads();
    for (int e = t; e < E_EDGES; e += 512) atomicAdd(&cnt[ei[e]], 1);
    __syncthreads();
    scn[t] = cnt[t];
    __syncthreads();
    #pragma unroll
    for (int d = 1; d < G1; d <<= 1) {
        int v = (t >= d) ? scn[t - d] : 0;
        __syncthreads();
        scn[t] += v;
        __syncthreads();
    }
    g_offsets[t + 1] = scn[t];            // inclusive -> shifted
    if (t == 0) g_offsets[0] = 0;
    cur[t] = scn[t] - cnt[t];             // exclusive offset = cursor base
    __syncthreads();
    for (int e = t; e < E_EDGES; e += 512) {
        int t0 = ei[e];
        int t1 = ei[E_EDGES + e];
        int pos = atomicAdd(&cur[t0], 1);
        g_edge_list[pos] = (t1 << 16) | e;
    }
}

// packed fp32x2 FMA: d.lo += a.lo*b.lo ; d.hi += a.hi*b.hi
__device__ __forceinline__ void fma2(ull& d, ull a, ull b) {
    asm("fma.rn.f32x2 %0, %1, %2, %0;" : "+l"(d) : "l"(a), "l"(b));
}
// duplicate a float into both lanes of a b64
__device__ __forceinline__ ull dupf(float f) {
    ull r;
    asm("mov.b64 %0, {%1, %1};" : "=l"(r) : "f"(f));
    return r;
}

union F2U  { ull u; float2 f; };
union V4U  { float4 f; ull u[2]; };

// -------- main SpMM kernel --------
// grid: 512 t0-blocks, 128 threads. Thread owns output rows b = tid and b = tid+128,
// ALL 16 output columns of this t0-block (8 fma2 accumulator pairs per row).
__global__ __launch_bounds__(128) void spmm_kernel(
    const float* __restrict__ x,
    const float* __restrict__ values,
    const float* __restrict__ bias,
    float* __restrict__ out)
{
    __shared__ __align__(16) float xs[2][256][PAD];   // x tile, natural layout, padded rows
    __shared__ __align__(16) float vs[2][256];        // raw V block, natural i*16+j layout

    const int tid = threadIdx.x;
    const int t0  = blockIdx.x;

    ull acc[8][2];
    #pragma unroll
    for (int jp = 0; jp < 8; jp++) { acc[jp][0] = 0ull; acc[jp][1] = 0ull; }

    const int beg = g_offsets[t0];
    const int end = g_offsets[t0 + 1];

    int c = 0;
    if (beg < end) {
        float4 XR[8];            // staged x tile slice (32 floats)
        float4 VR;               // staged v slice (tid < 64)

        // ---- prologue LDG for first edge ----
        {
            const int packed = g_edge_list[beg];
            const int e  = packed & 0xFFFF;
            const int t1 = packed >> 16;
            const float4* xg = reinterpret_cast<const float4*>(x + t1 * 16);
            #pragma unroll
            for (int q = 0; q < 8; q++) {
                const int lin = tid + (q << 7);
                XR[q] = __ldg(&xg[(size_t)(lin >> 2) * (S1 / 4) + (lin & 3)]);
            }
            if (tid < 64)
                VR = __ldg(reinterpret_cast<const float4*>(values + ((size_t)e << 8)) + tid);
        }

        for (int k = beg; k < end; k++) {
            // ---- STS stage edge k into buffer c (all natural-layout float4) ----
            #pragma unroll
            for (int q = 0; q < 8; q++) {
                const int lin = tid + (q << 7);
                *reinterpret_cast<float4*>(&xs[c][lin >> 2][(lin & 3) << 2]) = XR[q];
            }
            if (tid < 64)
                *reinterpret_cast<float4*>(&vs[c][tid << 2]) = VR;

            const int pnext = (k + 1 < end) ? g_edge_list[k + 1] : 0;

            __syncthreads();   // buffer c fully staged; also: all compute on c^1 finished

            // ---- LDG edge k+1 (overlaps compute below) ----
            if (k + 1 < end) {
                const int e  = pnext & 0xFFFF;
                const int t1 = pnext >> 16;
                const float4* xg = reinterpret_cast<const float4*>(x + t1 * 16);
                #pragma unroll
                for (int q = 0; q < 8; q++) {
                    const int lin = tid + (q << 7);
                    XR[q] = __ldg(&xg[(size_t)(lin >> 2) * (S1 / 4) + (lin & 3)]);
                }
                if (tid < 64)
                    VR = __ldg(reinterpret_cast<const float4*>(values + ((size_t)e << 8)) + tid);
            }

            // ---- compute on buffer c ----
            #pragma unroll
            for (int i4 = 0; i4 < 4; i4++) {
                const float4 x0 = *reinterpret_cast<const float4*>(&xs[c][tid      ][i4 << 2]);
                const float4 x1 = *reinterpret_cast<const float4*>(&xs[c][tid + 128][i4 << 2]);
                const float xf0[4] = {x0.x, x0.y, x0.z, x0.w};
                const float xf1[4] = {x1.x, x1.y, x1.z, x1.w};
                #pragma unroll
                for (int ii = 0; ii < 4; ii++) {
                    const int i = (i4 << 2) + ii;
                    const ull a0 = dupf(xf0[ii]);
                    const ull a1 = dupf(xf1[ii]);
                    V4U va, vb, vc2, vd;
                    va.f  = *reinterpret_cast<const float4*>(&vs[c][(i << 4) +  0]);
                    vb.f  = *reinterpret_cast<const float4*>(&vs[c][(i << 4) +  4]);
                    vc2.f = *reinterpret_cast<const float4*>(&vs[c][(i << 4) +  8]);
                    vd.f  = *reinterpret_cast<const float4*>(&vs[c][(i << 4) + 12]);
                    fma2(acc[0][0], a0, va.u[0]);  fma2(acc[0][1], a1, va.u[0]);
                    fma2(acc[1][0], a0, va.u[1]);  fma2(acc[1][1], a1, va.u[1]);
                    fma2(acc[2][0], a0, vb.u[0]);  fma2(acc[2][1], a1, vb.u[0]);
                    fma2(acc[3][0], a0, vb.u[1]);  fma2(acc[3][1], a1, vb.u[1]);
                    fma2(acc[4][0], a0, vc2.u[0]); fma2(acc[4][1], a1, vc2.u[0]);
                    fma2(acc[5][0], a0, vc2.u[1]); fma2(acc[5][1], a1, vc2.u[1]);
                    fma2(acc[6][0], a0, vd.u[0]);  fma2(acc[6][1], a1, vd.u[0]);
                    fma2(acc[7][0], a0, vd.u[1]);  fma2(acc[7][1], a1, vd.u[1]);
                }
            }
            c ^= 1;
        }
    }

    // ---- epilogue: bias + coalesced full-row stores (64 B per row) ----
    float bias_r[16];
    {
        const float4* bg4 = reinterpret_cast<const float4*>(bias + t0 * 16);
        #pragma unroll
        for (int m = 0; m < 4; m++) {
            float4 b4 = __ldg(&bg4[m]);
            bias_r[4 * m + 0] = b4.x; bias_r[4 * m + 1] = b4.y;
            bias_r[4 * m + 2] = b4.z; bias_r[4 * m + 3] = b4.w;
        }
    }
    #pragma unroll
    for (int t = 0; t < 2; t++) {
        const int b = tid + (t << 7);
        float o[16];
        #pragma unroll
        for (int jp = 0; jp < 8; jp++) {
            F2U u; u.u = acc[jp][t];
            o[2 * jp + 0] = u.f.x + bias_r[2 * jp + 0];
            o[2 * jp + 1] = u.f.y + bias_r[2 * jp + 1];
        }
        float* op = out + (size_t)b * S2 + t0 * 16;
        #pragma unroll
        for (int m = 0; m < 4; m++) {
            *reinterpret_cast<float4*>(op + 4 * m) =
                make_float4(o[4 * m], o[4 * m + 1], o[4 * m + 2], o[4 * m + 3]);
        }
    }
}

// -------- launch --------
extern "C" void kernel_launch(void* const* d_in, const int* in_sizes, int n_in,
                              void* d_out, int out_size) {
    const float* x      = (const float*)d_in[0];   // (256, 8192)
    const float* values = (const float*)d_in[1];   // (4194304,)
    const float* bias   = (const float*)d_in[2];   // (8192,)
    const int*   eidx   = (const int*)d_in[3];     // (2, 16384)
    float* out = (float*)d_out;                    // (256, 8192)

    bucket_kernel<<<1, 512>>>(eidx);
    spmm_kernel<<<G1, 128>>>(x, values, bias, out);
}

// round 4
// speedup vs baseline: 1.1337x; 1.1337x over previous
#include <cuda_runtime.h>
#include <cstdint>

// Problem dims
#define G1 512
#define E_EDGES 16384
#define S1 8192
#define S2 8192
#define PAD 20            // floats per staged x row (16 data + 4 pad, 16B-aligned, conflict-free)

typedef unsigned long long ull;

// -------- device scratch --------
__device__ int g_offsets[G1 + 1];
__device__ int g_edge_list[E_EDGES];   // packed: (t1 << 16) | e

// -------- fused precompute: histogram + scan + scatter, one CTA --------
__global__ __launch_bounds__(512) void bucket_kernel(const int* __restrict__ ei) {
    __shared__ int cnt[G1];
    __shared__ int scn[G1];
    __shared__ int cur[G1];
    const int t = threadIdx.x;
    cnt[t] = 0;
    __syncthreads();
    for (int e = t; e < E_EDGES; e += 512) atomicAdd(&cnt[ei[e]], 1);
    __syncthreads();
    scn[t] = cnt[t];
    __syncthreads();
    #pragma unroll
    for (int d = 1; d < G1; d <<= 1) {
        int v = (t >= d) ? scn[t - d] : 0;
        __syncthreads();
        scn[t] += v;
        __syncthreads();
    }
    g_offsets[t + 1] = scn[t];
    if (t == 0) g_offsets[0] = 0;
    cur[t] = scn[t] - cnt[t];
    __syncthreads();
    for (int e = t; e < E_EDGES; e += 512) {
        int t0 = ei[e];
        int t1 = ei[E_EDGES + e];
        int pos = atomicAdd(&cur[t0], 1);
        g_edge_list[pos] = (t1 << 16) | e;
    }
}

// packed fp32x2 FMA: d.lo += a.lo*b.lo ; d.hi += a.hi*b.hi
__device__ __forceinline__ void fma2(ull& d, ull a, ull b) {
    asm("fma.rn.f32x2 %0, %1, %2, %0;" : "+l"(d) : "l"(a), "l"(b));
}
__device__ __forceinline__ ull dupf(float f) {
    ull r;
    asm("mov.b64 %0, {%1, %1};" : "=l"(r) : "f"(f));
    return r;
}
__device__ __forceinline__ void cp16(uint32_t smem_dst, const void* gptr) {
    asm volatile("cp.async.cg.shared.global [%0], [%1], 16;" :: "r"(smem_dst), "l"(gptr));
}
__device__ __forceinline__ void cp_commit() {
    asm volatile("cp.async.commit_group;");
}
__device__ __forceinline__ void cp_wait1() {
    asm volatile("cp.async.wait_group 1;");
}

union F2U  { ull u; float2 f; };
union V4U  { float4 f; ull u[2]; };

// -------- main SpMM kernel --------
// grid: 512 t0-blocks, 128 threads. Thread owns batch rows tid and tid+128,
// all 16 output columns (8 fma2 accumulator pairs per row).
__global__ __launch_bounds__(128) void spmm_kernel(
    const float* __restrict__ x,
    const float* __restrict__ values,
    const float* __restrict__ bias,
    float* __restrict__ out)
{
    __shared__ __align__(16) float xs[2][256][PAD];   // 40 KB: double-buffered x tile
    __shared__ __align__(16) float vs[2][256];        //  2 KB: double-buffered V block

    const int tid = threadIdx.x;
    const int t0  = blockIdx.x;

    // smem addresses for cp.async (this thread's fixed destinations)
    uint32_t xdst[2][8];
    #pragma unroll
    for (int s = 0; s < 2; s++)
        #pragma unroll
        for (int q = 0; q < 8; q++) {
            const int lin = tid + (q << 7);
            xdst[s][q] = (uint32_t)__cvta_generic_to_shared(&xs[s][lin >> 2][(lin & 3) << 2]);
        }
    uint32_t vdst[2];
    vdst[0] = (uint32_t)__cvta_generic_to_shared(&vs[0][tid << 2]);
    vdst[1] = (uint32_t)__cvta_generic_to_shared(&vs[1][tid << 2]);

    ull acc[8][2];
    #pragma unroll
    for (int jp = 0; jp < 8; jp++) { acc[jp][0] = 0ull; acc[jp][1] = 0ull; }

    // preload bias (overlaps with everything)
    float bias_r[16];
    {
        const float4* bg4 = reinterpret_cast<const float4*>(bias + t0 * 16);
        #pragma unroll
        for (int m = 0; m < 4; m++) {
            float4 b4 = __ldg(&bg4[m]);
            bias_r[4 * m + 0] = b4.x; bias_r[4 * m + 1] = b4.y;
            bias_r[4 * m + 2] = b4.z; bias_r[4 * m + 3] = b4.w;
        }
    }

    const int beg = g_offsets[t0];
    const int end = g_offsets[t0 + 1];

    if (beg < end) {
        // ---- prologue: issue edge `beg` into buffer 0 ----
        {
            const int packed = g_edge_list[beg];
            const int e  = packed & 0xFFFF;
            const int t1 = packed >> 16;
            const float* xg = x + t1 * 16;
            #pragma unroll
            for (int q = 0; q < 8; q++) {
                const int lin = tid + (q << 7);
                cp16(xdst[0][q], xg + (size_t)(lin >> 2) * S1 + ((lin & 3) << 2));
            }
            if (tid < 64)
                cp16(vdst[0], values + ((size_t)e << 8) + (tid << 2));
            cp_commit();
        }

        for (int k = beg; k < end; k++) {
            const int c = (k - beg) & 1;

            __syncthreads();   // (A) all threads done computing edge k-1 -> buffer c^1 free

            // issue edge k+1 into buffer c^1
            if (k + 1 < end) {
                const int packed = g_edge_list[k + 1];
                const int e  = packed & 0xFFFF;
                const int t1 = packed >> 16;
                const float* xg = x + t1 * 16;
                #pragma unroll
                for (int q = 0; q < 8; q++) {
                    const int lin = tid + (q << 7);
                    cp16(xdst[c ^ 1][q], xg + (size_t)(lin >> 2) * S1 + ((lin & 3) << 2));
                }
                if (tid < 64)
                    cp16(vdst[c ^ 1], values + ((size_t)e << 8) + (tid << 2));
            }
            cp_commit();       // commit even if empty (keeps group counting aligned)
            cp_wait1();        // edge k's group complete (only k+1's group pending)

            __syncthreads();   // (B) edge k's data visible to all threads

            // ---- compute on buffer c ----
            #pragma unroll
            for (int i4 = 0; i4 < 4; i4++) {
                const float4 x0 = *reinterpret_cast<const float4*>(&xs[c][tid      ][i4 << 2]);
                const float4 x1 = *reinterpret_cast<const float4*>(&xs[c][tid + 128][i4 << 2]);
                const float xf0[4] = {x0.x, x0.y, x0.z, x0.w};
                const float xf1[4] = {x1.x, x1.y, x1.z, x1.w};
                #pragma unroll
                for (int ii = 0; ii < 4; ii++) {
                    const int i = (i4 << 2) + ii;
                    const ull a0 = dupf(xf0[ii]);
                    const ull a1 = dupf(xf1[ii]);
                    V4U va, vb, vc2, vd;
                    va.f  = *reinterpret_cast<const float4*>(&vs[c][(i << 4) +  0]);
                    vb.f  = *reinterpret_cast<const float4*>(&vs[c][(i << 4) +  4]);
                    vc2.f = *reinterpret_cast<const float4*>(&vs[c][(i << 4) +  8]);
                    vd.f  = *reinterpret_cast<const float4*>(&vs[c][(i << 4) + 12]);
                    fma2(acc[0][0], a0, va.u[0]);  fma2(acc[0][1], a1, va.u[0]);
                    fma2(acc[1][0], a0, va.u[1]);  fma2(acc[1][1], a1, va.u[1]);
                    fma2(acc[2][0], a0, vb.u[0]);  fma2(acc[2][1], a1, vb.u[0]);
                    fma2(acc[3][0], a0, vb.u[1]);  fma2(acc[3][1], a1, vb.u[1]);
                    fma2(acc[4][0], a0, vc2.u[0]); fma2(acc[4][1], a1, vc2.u[0]);
                    fma2(acc[5][0], a0, vc2.u[1]); fma2(acc[5][1], a1, vc2.u[1]);
                    fma2(acc[6][0], a0, vd.u[0]);  fma2(acc[6][1], a1, vd.u[0]);
                    fma2(acc[7][0], a0, vd.u[1]);  fma2(acc[7][1], a1, vd.u[1]);
                }
            }
        }
    }

    // ---- epilogue: bias + coalesced full-row stores ----
    #pragma unroll
    for (int t = 0; t < 2; t++) {
        const int b = tid + (t << 7);
        float o[16];
        #pragma unroll
        for (int jp = 0; jp < 8; jp++) {
            F2U u; u.u = acc[jp][t];
            o[2 * jp + 0] = u.f.x + bias_r[2 * jp + 0];
            o[2 * jp + 1] = u.f.y + bias_r[2 * jp + 1];
        }
        float* op = out + (size_t)b * S2 + t0 * 16;
        #pragma unroll
        for (int m = 0; m < 4; m++) {
            *reinterpret_cast<float4*>(op + 4 * m) =
                make_float4(o[4 * m], o[4 * m + 1], o[4 * m + 2], o[4 * m + 3]);
        }
    }
}

// -------- launch --------
extern "C" void kernel_launch(void* const* d_in, const int* in_sizes, int n_in,
                              void* d_out, int out_size) {
    const float* x      = (const float*)d_in[0];   // (256, 8192)
    const float* values = (const float*)d_in[1];   // (4194304,)
    const float* bias   = (const float*)d_in[2];   // (8192,)
    const int*   eidx   = (const int*)d_in[3];     // (2, 16384)
    float* out = (float*)d_out;                    // (256, 8192)

    bucket_kernel<<<1, 512>>>(eidx);
    spmm_kernel<<<G1, 128>>>(x, values, bias, out);
}